// round 1
// baseline (speedup 1.0000x reference)
#include <cuda_runtime.h>
#include <cuda_bf16.h>
#include <cstdint>

// Problem constants (fixed by the reference):
//   B = 32, P = 64, D = 34, L = 1048576
// inputs (metadata order): preds [B, L] f32, gts [B, P, D, 3] f32
// output: [B] f32
//
// out[b] = sum_{p,d valid} |preds[b, idx] - val| / (#persons with any valid dim)

#define RB   32
#define RP   64
#define RD   34
#define RL   1048576
#define NPD  (RP * RD)          // 2176 entries per batch
#define NTHREADS 256
#define PER_THREAD ((NPD + NTHREADS - 1) / NTHREADS)  // 9

__global__ __launch_bounds__(NTHREADS, 1)
void regl1_kernel(const float* __restrict__ preds,
                  const float* __restrict__ gts,
                  float* __restrict__ out)
{
    const int b   = blockIdx.x;
    const int tid = threadIdx.x;

    __shared__ float s_any[RP];       // per-person "has any valid dim" flag
    __shared__ float s_wsum[NTHREADS / 32];

    // zero person flags
    if (tid < RP) s_any[tid] = 0.0f;
    __syncthreads();

    const float* __restrict__ g  = gts   + (size_t)b * NPD * 3;
    const float* __restrict__ pr = preds + (size_t)b * RL;

    // Batch-issue all independent loads first (maximize MLP), then consume.
    float val[PER_THREAD];
    float flg[PER_THREAD];
    int   idx[PER_THREAD];

    #pragma unroll
    for (int j = 0; j < PER_THREAD; ++j) {
        const int i = tid + j * NTHREADS;
        if (i < NPD) {
            val[j] = g[i * 3 + 0];
            idx[j] = (int)g[i * 3 + 1];
            flg[j] = g[i * 3 + 2];
        } else {
            val[j] = 0.0f; idx[j] = 0; flg[j] = -1.0f;
        }
    }

    float gat[PER_THREAD];
    #pragma unroll
    for (int j = 0; j < PER_THREAD; ++j) {
        // gather only when valid; invalid lanes read slot 0 (in-bounds, discarded)
        gat[j] = __ldg(pr + (flg[j] > 0.0f ? idx[j] : 0));
    }

    float sum = 0.0f;
    #pragma unroll
    for (int j = 0; j < PER_THREAD; ++j) {
        const int i = tid + j * NTHREADS;
        if (i < NPD && flg[j] > 0.0f) {
            sum += fabsf(gat[j] - val[j]);
            s_any[i / RD] = 1.0f;   // benign race: all writers store 1.0f
        }
    }

    // intra-warp reduction
    #pragma unroll
    for (int off = 16; off > 0; off >>= 1)
        sum += __shfl_down_sync(0xFFFFFFFFu, sum, off);

    const int warp = tid >> 5;
    const int lane = tid & 31;
    if (lane == 0) s_wsum[warp] = sum;
    __syncthreads();

    if (warp == 0) {
        // total loss across the block's 8 warps
        float tot = (lane < (NTHREADS / 32)) ? s_wsum[lane] : 0.0f;
        #pragma unroll
        for (int off = 16; off > 0; off >>= 1)
            tot += __shfl_down_sync(0xFFFFFFFFu, tot, off);

        // num_people: sum of 64 person flags (2 per lane)
        float np = s_any[lane] + s_any[lane + 32];
        #pragma unroll
        for (int off = 16; off > 0; off >>= 1)
            np += __shfl_down_sync(0xFFFFFFFFu, np, off);

        if (lane == 0)
            out[b] = tot / np;   // reference guarantees np >= 1
    }
}

extern "C" void kernel_launch(void* const* d_in, const int* in_sizes, int n_in,
                              void* d_out, int out_size)
{
    const float* preds = (const float*)d_in[0];
    const float* gts   = (const float*)d_in[1];
    float* out         = (float*)d_out;
    regl1_kernel<<<RB, NTHREADS>>>(preds, gts, out);
}